// round 1
// baseline (speedup 1.0000x reference)
#include <cuda_runtime.h>
#include <math.h>

#define BSZ 8
#define NPTS 2048
#define KNN 20
#define EPS 1e-5f
#define SLOPE 0.2f

// ---------------- scratch (device globals; no runtime allocation) ----------------
__device__ float g_S[(long)BSZ * NPTS * NPTS];      // 134 MB score matrix (reused per layer)
__device__ float g_d2[BSZ * NPTS];
__device__ int   g_idx[BSZ * NPTS * KNN];
__device__ float g_YZ[(long)BSZ * NPTS * 512];      // max 2*O = 512 (layer 4)
__device__ float g_xc[(long)BSZ * NPTS * 512];      // concat(x1,x2,x3,x4)
__device__ float g_x5[(long)BSZ * NPTS * 1024];
__device__ float g_weff[512 * 128];                 // max [2O=512, C=128]
__device__ float g_g[BSZ * 2048];
__device__ float g_h1[BSZ * 512];
__device__ float g_h2[BSZ * 256];

// ---------------- d2 ----------------
__global__ void d2_kernel(const float* __restrict__ X, int ldx, int C,
                          float* __restrict__ d2, int total) {
    int i = blockIdx.x * blockDim.x + threadIdx.x;
    if (i >= total) return;
    const float* xr = X + (long)i * ldx;
    float s = 0.f;
    for (int c = 0; c < C; c++) { float v = xr[c]; s += v * v; }
    d2[i] = s;
}

// ---------------- generic GEMM: C = A(MxK, row lda) * B(NxK, row ldb)^T ----------------
// mode 0: raw; mode 1: 2*acc - d2[n] (gram score); mode 2: bn+leakyrelu epilogue
#define BM 64
#define BN 64
#define BK 16
__global__ void gemm_abT(const float* __restrict__ A, int lda, long bsA,
                         const float* __restrict__ Bm, int ldb, long bsB,
                         float* __restrict__ Cm, int ldc, long bsC,
                         int M, int Nn, int K,
                         const float* __restrict__ d2, long bsD2,
                         const float* __restrict__ bnp,
                         int mode) {
    const float* Ab = A + (long)blockIdx.z * bsA;
    const float* Bb = Bm + (long)blockIdx.z * bsB;
    float* Cb = Cm + (long)blockIdx.z * bsC;

    __shared__ float As[BK][BM];
    __shared__ float Bs[BK][BN];

    int tid = threadIdx.x;
    int tx = tid & 15, ty = tid >> 4;
    int bm = blockIdx.y * BM, bn = blockIdx.x * BN;

    float acc[4][4] = {};

    for (int k0 = 0; k0 < K; k0 += BK) {
#pragma unroll
        for (int e = 0; e < 4; e++) {
            int i = tid * 4 + e;
            int r = i >> 4, c = i & 15;
            float v = 0.f;
            if (k0 + c < K) v = Ab[(long)(bm + r) * lda + k0 + c];
            As[c][r] = v;
        }
#pragma unroll
        for (int e = 0; e < 4; e++) {
            int i = tid * 4 + e;
            int r = i >> 4, c = i & 15;
            float v = 0.f;
            if (k0 + c < K) v = Bb[(long)(bn + r) * ldb + k0 + c];
            Bs[c][r] = v;
        }
        __syncthreads();
#pragma unroll
        for (int kk = 0; kk < BK; kk++) {
            float4 a4 = *(const float4*)&As[kk][ty * 4];
            float4 b4 = *(const float4*)&Bs[kk][tx * 4];
            float av[4] = {a4.x, a4.y, a4.z, a4.w};
            float bv[4] = {b4.x, b4.y, b4.z, b4.w};
#pragma unroll
            for (int i = 0; i < 4; i++)
#pragma unroll
                for (int j = 0; j < 4; j++) acc[i][j] += av[i] * bv[j];
        }
        __syncthreads();
    }

#pragma unroll
    for (int i = 0; i < 4; i++) {
        int m = bm + ty * 4 + i;
#pragma unroll
        for (int j = 0; j < 4; j++) {
            int n_ = bn + tx * 4 + j;
            float v = acc[i][j];
            if (mode == 1) {
                v = 2.f * v - d2[(long)blockIdx.z * bsD2 + n_];
            } else if (mode == 2) {
                float gg = bnp[n_], be = bnp[Nn + n_], mm = bnp[2 * Nn + n_], vv = bnp[3 * Nn + n_];
                v = (v - mm) * (gg * rsqrtf(vv + EPS)) + be;
                v = v > 0.f ? v : SLOPE * v;
            }
            Cb[(long)m * ldc + n_] = v;
        }
    }
}

// ---------------- top-k (iterative argmax, k=20) ----------------
__global__ void topk_kernel(const float* __restrict__ S, int* __restrict__ idxo) {
    int row = blockIdx.x;  // b*2048 + n
    const float* s = S + (long)row * NPTS;
    __shared__ float sv[NPTS];
    __shared__ float rv[8];
    __shared__ int ri[8];
    int t = threadIdx.x;  // 256
    for (int j = t; j < NPTS; j += 256) sv[j] = s[j];
    __syncthreads();
    for (int r = 0; r < KNN; r++) {
        float best = -INFINITY;
        int bi = 0x7fffffff;
        for (int j = t; j < NPTS; j += 256) {
            float v = sv[j];
            if (v > best) { best = v; bi = j; }
        }
#pragma unroll
        for (int o = 16; o; o >>= 1) {
            float ov = __shfl_down_sync(0xffffffffu, best, o);
            int oi = __shfl_down_sync(0xffffffffu, bi, o);
            if (ov > best || (ov == best && oi < bi)) { best = ov; bi = oi; }
        }
        if ((t & 31) == 0) { rv[t >> 5] = best; ri[t >> 5] = bi; }
        __syncthreads();
        if (t == 0) {
            float bb = rv[0]; int bj = ri[0];
            for (int w = 1; w < 8; w++)
                if (rv[w] > bb || (rv[w] == bb && ri[w] < bj)) { bb = rv[w]; bj = ri[w]; }
            idxo[(long)row * KNN + r] = bj;
            sv[bj] = -INFINITY;
        }
        __syncthreads();
    }
}

// ---------------- build effective edge weights: [W1 ; W2 - W1] ----------------
__global__ void make_weff(const float* __restrict__ w, int O, int C,
                          float* __restrict__ weff) {
    int i = blockIdx.x * blockDim.x + threadIdx.x;
    if (i >= 2 * O * C) return;
    int row = i / C, c = i % C;
    if (row < O) weff[i] = w[row * 2 * C + c];
    else {
        int o = row - O;
        weff[i] = w[o * 2 * C + C + c] - w[o * 2 * C + c];
    }
}

// ---------------- gather neighbors' Y, max over k, add Z, bn+act ----------------
__global__ void gather_max(const float* __restrict__ YZ, int twoO,
                           const int* __restrict__ idxi,
                           const float* __restrict__ bnp,
                           float* __restrict__ out, int ldo, int O) {
    int n = blockIdx.x, b = blockIdx.y, o = threadIdx.x;
    __shared__ int si[KNN];
    if (o < KNN) si[o] = idxi[((long)b * NPTS + n) * KNN + o];
    __syncthreads();
    const float* Yb = YZ + (long)b * NPTS * twoO;
    float m = -INFINITY;
#pragma unroll 4
    for (int k = 0; k < KNN; k++) m = fmaxf(m, Yb[(long)si[k] * twoO + o]);
    float z = Yb[(long)n * twoO + O + o];
    float t = m + z;
    float gg = bnp[o], be = bnp[O + o], mm = bnp[2 * O + o], vv = bnp[3 * O + o];
    float v = (t - mm) * (gg * rsqrtf(vv + EPS)) + be;
    v = v > 0.f ? v : SLOPE * v;
    out[((long)b * NPTS + n) * ldo + o] = v;
}

// ---------------- global pool: max + mean over N ----------------
__global__ void pool_kernel(const float* __restrict__ x5, float* __restrict__ g) {
    int c = blockIdx.x * 256 + threadIdx.x;  // 0..1023
    int b = blockIdx.y;
    const float* p = x5 + (long)b * NPTS * 1024 + c;
    float mx = -INFINITY, sm = 0.f;
    for (int n = 0; n < NPTS; n++) {
        float v = p[(long)n * 1024];
        mx = fmaxf(mx, v);
        sm += v;
    }
    g[b * 2048 + c] = mx;
    g[b * 2048 + 1024 + c] = sm * (1.0f / NPTS);
}

// ---------------- small FC: out[b,o] = act?(bn?(in[b]·W[o] + bias?)) ----------------
__global__ void fc_kernel(const float* __restrict__ in, int K,
                          const float* __restrict__ W,
                          const float* __restrict__ bias,
                          const float* __restrict__ bnp, int useAct,
                          float* __restrict__ out, int O) {
    int o = blockIdx.x, b = blockIdx.y, t = threadIdx.x;  // block 128
    const float* xr = in + (long)b * K;
    const float* wr = W + (long)o * K;
    float s = 0.f;
    for (int k = t; k < K; k += 128) s += xr[k] * wr[k];
    __shared__ float red[4];
#pragma unroll
    for (int off = 16; off; off >>= 1) s += __shfl_down_sync(0xffffffffu, s, off);
    if ((t & 31) == 0) red[t >> 5] = s;
    __syncthreads();
    if (t == 0) {
        float tot = red[0] + red[1] + red[2] + red[3];
        if (bias) tot += bias[o];
        if (bnp) {
            float gg = bnp[o], be = bnp[O + o], mm = bnp[2 * O + o], vv = bnp[3 * O + o];
            tot = (tot - mm) * (gg * rsqrtf(vv + EPS)) + be;
        }
        if (useAct) tot = tot > 0.f ? tot : SLOPE * tot;
        out[(long)b * O + o] = tot;
    }
}

extern "C" void kernel_launch(void* const* d_in, const int* in_sizes, int n_in,
                              void* d_out, int out_size) {
    const float* x   = (const float*)d_in[0];
    // d_in[1] = normal (unused)
    const float* w1  = (const float*)d_in[2];
    const float* w2  = (const float*)d_in[3];
    const float* w3  = (const float*)d_in[4];
    const float* w4  = (const float*)d_in[5];
    const float* w5  = (const float*)d_in[6];
    const float* wl1 = (const float*)d_in[7];
    const float* wl2 = (const float*)d_in[8];
    const float* bl2 = (const float*)d_in[9];
    const float* wl3 = (const float*)d_in[10];
    const float* bl3 = (const float*)d_in[11];
    const float* bn1 = (const float*)d_in[12];
    const float* bn2 = (const float*)d_in[13];
    const float* bn3 = (const float*)d_in[14];
    const float* bn4 = (const float*)d_in[15];
    const float* bn5 = (const float*)d_in[16];
    const float* bn6 = (const float*)d_in[17];
    const float* bn7 = (const float*)d_in[18];

    float *S, *d2, *YZ, *xc, *x5, *weff, *gb, *h1, *h2;
    int* idx;
    cudaGetSymbolAddress((void**)&S, g_S);
    cudaGetSymbolAddress((void**)&d2, g_d2);
    cudaGetSymbolAddress((void**)&idx, g_idx);
    cudaGetSymbolAddress((void**)&YZ, g_YZ);
    cudaGetSymbolAddress((void**)&xc, g_xc);
    cudaGetSymbolAddress((void**)&x5, g_x5);
    cudaGetSymbolAddress((void**)&weff, g_weff);
    cudaGetSymbolAddress((void**)&gb, g_g);
    cudaGetSymbolAddress((void**)&h1, g_h1);
    cudaGetSymbolAddress((void**)&h2, g_h2);

    struct LayerCfg { const float* in; int lda; const float* w; int C, O; const float* bn; int off; };
    LayerCfg L[4] = {
        { x,        3,   w1, 3,   64,  bn1, 0   },
        { xc + 0,   512, w2, 64,  64,  bn2, 64  },
        { xc + 64,  512, w3, 64,  128, bn3, 128 },
        { xc + 128, 512, w4, 128, 256, bn4, 256 },
    };

    const int TOTAL = BSZ * NPTS;  // 16384

    for (int l = 0; l < 4; l++) {
        const LayerCfg& c = L[l];
        // ||x_j||^2
        d2_kernel<<<TOTAL / 256, 256>>>(c.in, c.lda, c.C, d2, TOTAL);
        // Gram scores S[b,n,j] = 2 x_n.x_j - d2[j]  (batched)
        dim3 gg(NPTS / BN, NPTS / BM, BSZ);
        gemm_abT<<<gg, 256>>>(c.in, c.lda, (long)NPTS * c.lda,
                              c.in, c.lda, (long)NPTS * c.lda,
                              S, NPTS, (long)NPTS * NPTS,
                              NPTS, NPTS, c.C,
                              d2, NPTS, nullptr, 1);
        // top-20 neighbors per row
        topk_kernel<<<TOTAL, 256>>>(S, idx);
        // effective weights [W1; W2-W1]
        make_weff<<<(2 * c.O * c.C + 255) / 256, 256>>>(c.w, c.O, c.C, weff);
        // YZ = X * Weff^T   (M = 16384, N = 2O, K = C)
        dim3 g2(2 * c.O / BN, TOTAL / BM, 1);
        gemm_abT<<<g2, 256>>>(c.in, c.lda, 0,
                              weff, c.C, 0,
                              YZ, 2 * c.O, 0,
                              TOTAL, 2 * c.O, c.C,
                              nullptr, 0, nullptr, 0);
        // out = act(bn(max_k Y[idx] + Z)) -> xc slice
        gather_max<<<dim3(NPTS, BSZ), c.O>>>(YZ, 2 * c.O, idx, c.bn, xc + c.off, 512, c.O);
    }

    // x5 = act(bn5(xc @ w5^T))   [16384, 512] x [1024, 512]
    gemm_abT<<<dim3(1024 / BN, TOTAL / BM, 1), 256>>>(
        xc, 512, 0, w5, 512, 0, x5, 1024, 0,
        TOTAL, 1024, 512, nullptr, 0, bn5, 2);

    // global max+mean pool -> g [8, 2048]
    pool_kernel<<<dim3(4, BSZ), 256>>>(x5, gb);

    // FC stack
    fc_kernel<<<dim3(512, BSZ), 128>>>(gb, 2048, wl1, nullptr, bn6, 1, h1, 512);
    fc_kernel<<<dim3(256, BSZ), 128>>>(h1, 512, wl2, bl2, bn7, 1, h2, 256);
    fc_kernel<<<dim3(40, BSZ), 128>>>(h2, 256, wl3, bl3, nullptr, 0, (float*)d_out, 40);
}

// round 2
// speedup vs baseline: 1.6144x; 1.6144x over previous
#include <cuda_runtime.h>
#include <math.h>

#define BSZ 8
#define NPTS 2048
#define KNN 20
#define EPS 1e-5f
#define SLOPE 0.2f

// ---------------- scratch (device globals; no runtime allocation) ----------------
__device__ float g_S[(long)BSZ * NPTS * NPTS];      // 134 MB score matrix (reused per layer)
__device__ float g_d2[BSZ * NPTS];
__device__ int   g_idx[BSZ * NPTS * KNN];
__device__ float g_YZ[(long)BSZ * NPTS * 512];
__device__ float g_xc[(long)BSZ * NPTS * 512];
__device__ float g_x5[(long)BSZ * NPTS * 1024];
__device__ float g_weff[512 * 128];
__device__ float g_g[BSZ * 2048];
__device__ float g_h1[BSZ * 512];
__device__ float g_h2[BSZ * 256];

// ---------------- d2 ----------------
__global__ void d2_kernel(const float* __restrict__ X, int ldx, int C,
                          float* __restrict__ d2, int total) {
    int i = blockIdx.x * blockDim.x + threadIdx.x;
    if (i >= total) return;
    const float* xr = X + (long)i * ldx;
    float s = 0.f;
    for (int c = 0; c < C; c++) { float v = xr[c]; s += v * v; }
    d2[i] = s;
}

// ---------------- GEMM: C = A(MxK) * B(NxK)^T, 128x128x8 tile, 8x8/thread ----------
// mode 0: raw; mode 1: 2*acc - d2[n]; mode 2: bn+leakyrelu
#define BM 128
#define BN 128
#define BK 8
__global__ __launch_bounds__(256) void gemm_abT(
        const float* __restrict__ A, int lda, long bsA,
        const float* __restrict__ Bm, int ldb, long bsB,
        float* __restrict__ Cm, int ldc, long bsC,
        int M, int Nn, int K,
        const float* __restrict__ d2, long bsD2,
        const float* __restrict__ bnp, int mode) {
    const float* Ab = A + (long)blockIdx.z * bsA;
    const float* Bb = Bm + (long)blockIdx.z * bsB;
    float* Cb = Cm + (long)blockIdx.z * bsC;

    __shared__ float As[BK][BM + 4];
    __shared__ float Bs[BK][BN + 4];

    int tid = threadIdx.x;
    int tx = tid & 15, ty = tid >> 4;
    int bm = blockIdx.y * BM, bn = blockIdx.x * BN;

    int lk = tid & 7;       // k within tile
    int lm = tid >> 3;      // 0..31 -> rows lm, lm+32, lm+64, lm+96

    float ra[4], rb[4];
    float acc[8][8] = {};

    // prefetch tile 0
#pragma unroll
    for (int i = 0; i < 4; i++) {
        int m = lm + i * 32;
        ra[i] = (lk < K) ? Ab[(long)(bm + m) * lda + lk] : 0.f;
        rb[i] = (lk < K) ? Bb[(long)(bn + m) * ldb + lk] : 0.f;
    }

    for (int k0 = 0; k0 < K; k0 += BK) {
#pragma unroll
        for (int i = 0; i < 4; i++) {
            As[lk][lm + i * 32] = ra[i];
            Bs[lk][lm + i * 32] = rb[i];
        }
        __syncthreads();
        int kn = k0 + BK;
        if (kn < K) {
#pragma unroll
            for (int i = 0; i < 4; i++) {
                int m = lm + i * 32;
                ra[i] = (kn + lk < K) ? Ab[(long)(bm + m) * lda + kn + lk] : 0.f;
                rb[i] = (kn + lk < K) ? Bb[(long)(bn + m) * ldb + kn + lk] : 0.f;
            }
        }
#pragma unroll
        for (int kk = 0; kk < BK; kk++) {
            float4 a0 = *(const float4*)&As[kk][ty * 4];
            float4 a1 = *(const float4*)&As[kk][64 + ty * 4];
            float4 b0 = *(const float4*)&Bs[kk][tx * 4];
            float4 b1 = *(const float4*)&Bs[kk][64 + tx * 4];
            float av[8] = {a0.x, a0.y, a0.z, a0.w, a1.x, a1.y, a1.z, a1.w};
            float bv[8] = {b0.x, b0.y, b0.z, b0.w, b1.x, b1.y, b1.z, b1.w};
#pragma unroll
            for (int i = 0; i < 8; i++)
#pragma unroll
                for (int j = 0; j < 8; j++) acc[i][j] += av[i] * bv[j];
        }
        __syncthreads();
    }

#pragma unroll
    for (int i = 0; i < 8; i++) {
        int m = bm + (i < 4 ? ty * 4 + i : 64 + ty * 4 + (i - 4));
#pragma unroll
        for (int j = 0; j < 8; j++) {
            int n_ = bn + (j < 4 ? tx * 4 + j : 64 + tx * 4 + (j - 4));
            float v = acc[i][j];
            if (mode == 1) {
                v = 2.f * v - d2[(long)blockIdx.z * bsD2 + n_];
            } else if (mode == 2) {
                float gg = bnp[n_], be = bnp[Nn + n_], mm = bnp[2 * Nn + n_], vv = bnp[3 * Nn + n_];
                v = (v - mm) * (gg * rsqrtf(vv + EPS)) + be;
                v = v > 0.f ? v : SLOPE * v;
            }
            Cb[(long)m * ldc + n_] = v;
        }
    }
}

// ---------------- top-k: one warp per row, register-resident ----------------
__global__ __launch_bounds__(256) void topk_kernel(const float* __restrict__ S,
                                                   int* __restrict__ idxo) {
    int warp = threadIdx.x >> 5, lane = threadIdx.x & 31;
    int row = blockIdx.x * 8 + warp;
    const float* s = S + (long)row * NPTS;

    float r[64];
#pragma unroll
    for (int j = 0; j < 64; j++) r[j] = s[j * 32 + lane];

    for (int it = 0; it < KNN; it++) {
        float best = -INFINITY;
        int bj = 0;
#pragma unroll
        for (int j = 0; j < 64; j++) {
            if (r[j] > best) { best = r[j]; bj = j; }
        }
        int bidx = bj * 32 + lane;
#pragma unroll
        for (int o = 16; o; o >>= 1) {
            float ov = __shfl_down_sync(0xffffffffu, best, o);
            int oi = __shfl_down_sync(0xffffffffu, bidx, o);
            if (ov > best || (ov == best && oi < bidx)) { best = ov; bidx = oi; }
        }
        bidx = __shfl_sync(0xffffffffu, bidx, 0);
        if (lane == 0) idxo[(long)row * KNN + it] = bidx;
        if ((bidx & 31) == lane) {
            int jw = bidx >> 5;
#pragma unroll
            for (int j = 0; j < 64; j++)
                if (j == jw) r[j] = -INFINITY;
        }
    }
}

// ---------------- build effective edge weights: [W1 ; W2 - W1] ----------------
__global__ void make_weff(const float* __restrict__ w, int O, int C,
                          float* __restrict__ weff) {
    int i = blockIdx.x * blockDim.x + threadIdx.x;
    if (i >= 2 * O * C) return;
    int row = i / C, c = i % C;
    if (row < O) weff[i] = w[row * 2 * C + c];
    else {
        int o = row - O;
        weff[i] = w[o * 2 * C + C + c] - w[o * 2 * C + c];
    }
}

// ---------------- gather neighbors' Y, max over k, add Z, bn+act ----------------
__global__ void gather_max(const float* __restrict__ YZ, int twoO,
                           const int* __restrict__ idxi,
                           const float* __restrict__ bnp,
                           float* __restrict__ out, int ldo, int O) {
    int n = blockIdx.x, b = blockIdx.y, o = threadIdx.x;
    __shared__ int si[KNN];
    if (o < KNN) si[o] = idxi[((long)b * NPTS + n) * KNN + o];
    __syncthreads();
    const float* Yb = YZ + (long)b * NPTS * twoO;
    float m = -INFINITY;
#pragma unroll 4
    for (int k = 0; k < KNN; k++) m = fmaxf(m, Yb[(long)si[k] * twoO + o]);
    float z = Yb[(long)n * twoO + O + o];
    float t = m + z;
    float gg = bnp[o], be = bnp[O + o], mm = bnp[2 * O + o], vv = bnp[3 * O + o];
    float v = (t - mm) * (gg * rsqrtf(vv + EPS)) + be;
    v = v > 0.f ? v : SLOPE * v;
    out[((long)b * NPTS + n) * ldo + o] = v;
}

// ---------------- global pool: max + mean over N ----------------
__global__ void pool_kernel(const float* __restrict__ x5, float* __restrict__ g) {
    int c = blockIdx.x * 256 + threadIdx.x;
    int b = blockIdx.y;
    const float* p = x5 + (long)b * NPTS * 1024 + c;
    float mx = -INFINITY, sm = 0.f;
    for (int n = 0; n < NPTS; n++) {
        float v = p[(long)n * 1024];
        mx = fmaxf(mx, v);
        sm += v;
    }
    g[b * 2048 + c] = mx;
    g[b * 2048 + 1024 + c] = sm * (1.0f / NPTS);
}

// ---------------- small FC ----------------
__global__ void fc_kernel(const float* __restrict__ in, int K,
                          const float* __restrict__ W,
                          const float* __restrict__ bias,
                          const float* __restrict__ bnp, int useAct,
                          float* __restrict__ out, int O) {
    int o = blockIdx.x, b = blockIdx.y, t = threadIdx.x;
    const float* xr = in + (long)b * K;
    const float* wr = W + (long)o * K;
    float s = 0.f;
    for (int k = t; k < K; k += 128) s += xr[k] * wr[k];
    __shared__ float red[4];
#pragma unroll
    for (int off = 16; off; off >>= 1) s += __shfl_down_sync(0xffffffffu, s, off);
    if ((t & 31) == 0) red[t >> 5] = s;
    __syncthreads();
    if (t == 0) {
        float tot = red[0] + red[1] + red[2] + red[3];
        if (bias) tot += bias[o];
        if (bnp) {
            float gg = bnp[o], be = bnp[O + o], mm = bnp[2 * O + o], vv = bnp[3 * O + o];
            tot = (tot - mm) * (gg * rsqrtf(vv + EPS)) + be;
        }
        if (useAct) tot = tot > 0.f ? tot : SLOPE * tot;
        out[(long)b * O + o] = tot;
    }
}

extern "C" void kernel_launch(void* const* d_in, const int* in_sizes, int n_in,
                              void* d_out, int out_size) {
    const float* x   = (const float*)d_in[0];
    const float* w1  = (const float*)d_in[2];
    const float* w2  = (const float*)d_in[3];
    const float* w3  = (const float*)d_in[4];
    const float* w4  = (const float*)d_in[5];
    const float* w5  = (const float*)d_in[6];
    const float* wl1 = (const float*)d_in[7];
    const float* wl2 = (const float*)d_in[8];
    const float* bl2 = (const float*)d_in[9];
    const float* wl3 = (const float*)d_in[10];
    const float* bl3 = (const float*)d_in[11];
    const float* bn1 = (const float*)d_in[12];
    const float* bn2 = (const float*)d_in[13];
    const float* bn3 = (const float*)d_in[14];
    const float* bn4 = (const float*)d_in[15];
    const float* bn5 = (const float*)d_in[16];
    const float* bn6 = (const float*)d_in[17];
    const float* bn7 = (const float*)d_in[18];

    float *S, *d2, *YZ, *xc, *x5, *weff, *gb, *h1, *h2;
    int* idx;
    cudaGetSymbolAddress((void**)&S, g_S);
    cudaGetSymbolAddress((void**)&d2, g_d2);
    cudaGetSymbolAddress((void**)&idx, g_idx);
    cudaGetSymbolAddress((void**)&YZ, g_YZ);
    cudaGetSymbolAddress((void**)&xc, g_xc);
    cudaGetSymbolAddress((void**)&x5, g_x5);
    cudaGetSymbolAddress((void**)&weff, g_weff);
    cudaGetSymbolAddress((void**)&gb, g_g);
    cudaGetSymbolAddress((void**)&h1, g_h1);
    cudaGetSymbolAddress((void**)&h2, g_h2);

    struct LayerCfg { const float* in; int lda; const float* w; int C, O; const float* bn; int off; };
    LayerCfg L[4] = {
        { x,        3,   w1, 3,   64,  bn1, 0   },
        { xc + 0,   512, w2, 64,  64,  bn2, 64  },
        { xc + 64,  512, w3, 64,  128, bn3, 128 },
        { xc + 128, 512, w4, 128, 256, bn4, 256 },
    };

    const int TOTAL = BSZ * NPTS;  // 16384

    for (int l = 0; l < 4; l++) {
        const LayerCfg& c = L[l];
        d2_kernel<<<TOTAL / 256, 256>>>(c.in, c.lda, c.C, d2, TOTAL);
        dim3 gg(NPTS / BN, NPTS / BM, BSZ);
        gemm_abT<<<gg, 256>>>(c.in, c.lda, (long)NPTS * c.lda,
                              c.in, c.lda, (long)NPTS * c.lda,
                              S, NPTS, (long)NPTS * NPTS,
                              NPTS, NPTS, c.C,
                              d2, NPTS, nullptr, 1);
        topk_kernel<<<TOTAL / 8, 256>>>(S, idx);
        make_weff<<<(2 * c.O * c.C + 255) / 256, 256>>>(c.w, c.O, c.C, weff);
        dim3 g2(2 * c.O / BN, TOTAL / BM, 1);
        gemm_abT<<<g2, 256>>>(c.in, c.lda, 0,
                              weff, c.C, 0,
                              YZ, 2 * c.O, 0,
                              TOTAL, 2 * c.O, c.C,
                              nullptr, 0, nullptr, 0);
        gather_max<<<dim3(NPTS, BSZ), c.O>>>(YZ, 2 * c.O, idx, c.bn, xc + c.off, 512, c.O);
    }

    gemm_abT<<<dim3(1024 / BN, TOTAL / BM, 1), 256>>>(
        xc, 512, 0, w5, 512, 0, x5, 1024, 0,
        TOTAL, 1024, 512, nullptr, 0, bn5, 2);

    pool_kernel<<<dim3(4, BSZ), 256>>>(x5, gb);

    fc_kernel<<<dim3(512, BSZ), 128>>>(gb, 2048, wl1, nullptr, bn6, 1, h1, 512);
    fc_kernel<<<dim3(256, BSZ), 128>>>(h1, 512, wl2, bl2, bn7, 1, h2, 256);
    fc_kernel<<<dim3(40, BSZ), 128>>>(h2, 256, wl3, bl3, nullptr, 0, (float*)d_out, 40);
}

// round 4
// speedup vs baseline: 2.3445x; 1.4522x over previous
#include <cuda_runtime.h>
#include <cuda_fp16.h>
#include <cstdint>
#include <math.h>

#define BSZ 8
#define NPTS 2048
#define KNN 20
#define EPS 1e-5f
#define SLOPE 0.2f

// ---------------- scratch (device globals; no runtime allocation) ----------------
__device__ float g_S[(long)BSZ * NPTS * NPTS];
__device__ float g_d2[BSZ * NPTS];
__device__ int   g_idx[BSZ * NPTS * KNN];
__device__ float g_YZ[(long)BSZ * NPTS * 512];
__device__ float g_xc[(long)BSZ * NPTS * 512];
__device__ float g_x5[(long)BSZ * NPTS * 1024];
__device__ float g_weff[512 * 128];
__device__ float g_g[BSZ * 2048];
__device__ float g_h1[BSZ * 512];
__device__ float g_h2[BSZ * 256];
// fp16 hi/lo split buffers
__device__ __align__(16) unsigned short g_Xh[(long)BSZ * NPTS * 128];
__device__ __align__(16) unsigned short g_Xl[(long)BSZ * NPTS * 128];
__device__ __align__(16) unsigned short g_XCh[(long)BSZ * NPTS * 512];
__device__ __align__(16) unsigned short g_XCl[(long)BSZ * NPTS * 512];
__device__ __align__(16) unsigned short g_W5h[1024 * 512];
__device__ __align__(16) unsigned short g_W5l[1024 * 512];
__device__ __align__(16) unsigned short g_Wh[512 * 128];
__device__ __align__(16) unsigned short g_Wl[512 * 128];

__device__ __forceinline__ uint32_t smem_u32(const void* p) {
    uint32_t a;
    asm("{ .reg .u64 t; cvta.to.shared.u64 t, %1; cvt.u32.u64 %0, t; }" : "=r"(a) : "l"(p));
    return a;
}

#define LDSM4(f, addr) \
    asm volatile("ldmatrix.sync.aligned.m8n8.x4.shared.b16 {%0,%1,%2,%3}, [%4];" \
                 : "=r"((f)[0]), "=r"((f)[1]), "=r"((f)[2]), "=r"((f)[3]) : "r"(addr))

#define MMA16816(c, a, b0, b1) \
    asm volatile("mma.sync.aligned.m16n8k16.row.col.f32.f16.f16.f32 " \
                 "{%0,%1,%2,%3}, {%4,%5,%6,%7}, {%8,%9}, {%0,%1,%2,%3};" \
                 : "+f"((c)[0]), "+f"((c)[1]), "+f"((c)[2]), "+f"((c)[3]) \
                 : "r"((a)[0]), "r"((a)[1]), "r"((a)[2]), "r"((a)[3]), "r"(b0), "r"(b1))

// ======================= HMMA split-fp16 GEMM =======================
// C[M,N] = A[M,K] * B[N,K]^T, A/B as fp16 hi/lo pairs (hh+hl+lh, fp32 accum).
// Block tile 128x128, 8 warps (64x32 each), K chunk 32.
// mode 0: raw; 1: 2v - d2[col]; 2: bn+leakyrelu.
__global__ __launch_bounds__(256) void gemm_mma(
        const unsigned short* __restrict__ Ah0, const unsigned short* __restrict__ Al0, long bsA,
        const unsigned short* __restrict__ Bh0, const unsigned short* __restrict__ Bl0, long bsB,
        float* __restrict__ Cm, int ldc, long bsC,
        int K, const float* __restrict__ d2, const float* __restrict__ bnp,
        int Nn, int mode) {
    __shared__ __align__(16) char smA_h[8192];
    __shared__ __align__(16) char smA_l[8192];
    __shared__ __align__(16) char smB_h[8192];
    __shared__ __align__(16) char smB_l[8192];

    int tid = threadIdx.x, wid = tid >> 5, lane = tid & 31;
    int bm = blockIdx.y * 128, bn = blockIdx.x * 128, z = blockIdx.z;

    const unsigned short* Ah = Ah0 + (long)z * bsA;
    const unsigned short* Al = Al0 + (long)z * bsA;
    const unsigned short* Bh = Bh0 + (long)z * bsB;
    const unsigned short* Bl = Bl0 + (long)z * bsB;
    float* Cb = Cm + (long)z * bsC;

    int wm = (wid >> 2) * 64, wn = (wid & 3) * 32;

    // ldmatrix lane address components
    int a_r = lane & 15, a_kh = lane >> 4;                    // A: rows 0..15, k-half
    int b_n = (lane & 7) + ((lane >> 4) << 3), b_kh = (lane >> 3) & 1;  // B

    uint32_t sAh = smem_u32(smA_h), sAl = smem_u32(smA_l);
    uint32_t sBh = smem_u32(smB_h), sBl = smem_u32(smB_l);

    float acc[4][4][4] = {};

    for (int k0 = 0; k0 < K; k0 += 32) {
#pragma unroll
        for (int i = 0; i < 2; i++) {
            int q = tid + i * 256;           // 0..511  (128 rows x 4 16B-chunks)
            int r = q >> 2, ci = q & 3;
            int phys = r * 64 + ((ci ^ ((r >> 1) & 3)) * 16);
            long ga = (long)(bm + r) * K + k0 + ci * 8;
            long gb = (long)(bn + r) * K + k0 + ci * 8;
            *(uint4*)(smA_h + phys) = *(const uint4*)(Ah + ga);
            *(uint4*)(smA_l + phys) = *(const uint4*)(Al + ga);
            *(uint4*)(smB_h + phys) = *(const uint4*)(Bh + gb);
            *(uint4*)(smB_l + phys) = *(const uint4*)(Bl + gb);
        }
        __syncthreads();
#pragma unroll
        for (int s = 0; s < 2; s++) {
            uint32_t af[4][4], bfh[2][4], bfl[2][4];
            // A-hi fragments
#pragma unroll
            for (int mt = 0; mt < 4; mt++) {
                int row = wm + mt * 16 + a_r;
                int ch = 2 * s + a_kh;
                LDSM4(af[mt], sAh + row * 64 + ((ch ^ ((row >> 1) & 3)) * 16));
            }
            // B-hi fragments
#pragma unroll
            for (int g = 0; g < 2; g++) {
                int row = wn + g * 16 + b_n;
                int ch = 2 * s + b_kh;
                LDSM4(bfh[g], sBh + row * 64 + ((ch ^ ((row >> 1) & 3)) * 16));
            }
            // hh
#pragma unroll
            for (int mt = 0; mt < 4; mt++)
#pragma unroll
                for (int nt = 0; nt < 4; nt++)
                    MMA16816(acc[mt][nt], af[mt], bfh[nt >> 1][(nt & 1) * 2], bfh[nt >> 1][(nt & 1) * 2 + 1]);
            // B-lo fragments, hl
#pragma unroll
            for (int g = 0; g < 2; g++) {
                int row = wn + g * 16 + b_n;
                int ch = 2 * s + b_kh;
                LDSM4(bfl[g], sBl + row * 64 + ((ch ^ ((row >> 1) & 3)) * 16));
            }
#pragma unroll
            for (int mt = 0; mt < 4; mt++)
#pragma unroll
                for (int nt = 0; nt < 4; nt++)
                    MMA16816(acc[mt][nt], af[mt], bfl[nt >> 1][(nt & 1) * 2], bfl[nt >> 1][(nt & 1) * 2 + 1]);
            // A-lo fragments (reuse af regs), lh with B-hi
#pragma unroll
            for (int mt = 0; mt < 4; mt++) {
                int row = wm + mt * 16 + a_r;
                int ch = 2 * s + a_kh;
                LDSM4(af[mt], sAl + row * 64 + ((ch ^ ((row >> 1) & 3)) * 16));
            }
#pragma unroll
            for (int mt = 0; mt < 4; mt++)
#pragma unroll
                for (int nt = 0; nt < 4; nt++)
                    MMA16816(acc[mt][nt], af[mt], bfh[nt >> 1][(nt & 1) * 2], bfh[nt >> 1][(nt & 1) * 2 + 1]);
        }
        __syncthreads();
    }

    // epilogue
#pragma unroll
    for (int mt = 0; mt < 4; mt++) {
        int r0 = bm + wm + mt * 16 + (lane >> 2);
#pragma unroll
        for (int h = 0; h < 2; h++) {
            int row = r0 + h * 8;
#pragma unroll
            for (int nt = 0; nt < 4; nt++) {
                int col = bn + wn + nt * 8 + (lane & 3) * 2;
                float v0 = acc[mt][nt][h * 2];
                float v1 = acc[mt][nt][h * 2 + 1];
                if (mode == 1) {
                    const float* dd = d2 + (long)z * NPTS;
                    v0 = 2.f * v0 - dd[col];
                    v1 = 2.f * v1 - dd[col + 1];
                } else if (mode == 2) {
                    float gg = bnp[col], be = bnp[Nn + col];
                    float mm = bnp[2 * Nn + col], vv = bnp[3 * Nn + col];
                    v0 = (v0 - mm) * (gg * rsqrtf(vv + EPS)) + be;
                    v0 = v0 > 0.f ? v0 : SLOPE * v0;
                    gg = bnp[col + 1]; be = bnp[Nn + col + 1];
                    mm = bnp[2 * Nn + col + 1]; vv = bnp[3 * Nn + col + 1];
                    v1 = (v1 - mm) * (gg * rsqrtf(vv + EPS)) + be;
                    v1 = v1 > 0.f ? v1 : SLOPE * v1;
                }
                *(float2*)&Cb[(long)row * ldc + col] = make_float2(v0, v1);
            }
        }
    }
}

// ======================= fp32 -> fp16 hi/lo split =======================
__global__ void split_kernel(const float* __restrict__ src, int ld, int C, int rows,
                             unsigned short* __restrict__ hi, unsigned short* __restrict__ lo) {
    long i = (long)blockIdx.x * blockDim.x + threadIdx.x;
    if (i >= (long)rows * C) return;
    int r = (int)(i / C), c = (int)(i % C);
    float v = src[(long)r * ld + c];
    __half h = __float2half_rn(v);
    __half l = __float2half_rn(v - __half2float(h));
    hi[i] = *(unsigned short*)&h;
    lo[i] = *(unsigned short*)&l;
}

__global__ void make_weff_split(const float* __restrict__ w, int O, int C,
                                unsigned short* __restrict__ hi, unsigned short* __restrict__ lo) {
    int i = blockIdx.x * blockDim.x + threadIdx.x;
    if (i >= 2 * O * C) return;
    int row = i / C, c = i % C;
    float v;
    if (row < O) v = w[row * 2 * C + c];
    else { int o = row - O; v = w[o * 2 * C + C + c] - w[o * 2 * C + c]; }
    __half h = __float2half_rn(v);
    __half l = __float2half_rn(v - __half2float(h));
    hi[i] = *(unsigned short*)&h;
    lo[i] = *(unsigned short*)&l;
}

// ======================= fp32 SIMT GEMM (layer 1 only) =======================
#define BM 128
#define BN 128
#define BK 8
__global__ __launch_bounds__(256) void gemm_abT(
        const float* __restrict__ A, int lda, long bsA,
        const float* __restrict__ Bm, int ldb, long bsB,
        float* __restrict__ Cm, int ldc, long bsC,
        int M, int Nn, int K,
        const float* __restrict__ d2, long bsD2,
        const float* __restrict__ bnp, int mode) {
    const float* Ab = A + (long)blockIdx.z * bsA;
    const float* Bb = Bm + (long)blockIdx.z * bsB;
    float* Cb = Cm + (long)blockIdx.z * bsC;

    __shared__ float As[BK][BM + 4];
    __shared__ float Bs[BK][BN + 4];

    int tid = threadIdx.x;
    int tx = tid & 15, ty = tid >> 4;
    int bm = blockIdx.y * BM, bn = blockIdx.x * BN;
    int lk = tid & 7, lm = tid >> 3;

    float ra[4], rb[4];
    float acc[8][8] = {};

#pragma unroll
    for (int i = 0; i < 4; i++) {
        int m = lm + i * 32;
        ra[i] = (lk < K) ? Ab[(long)(bm + m) * lda + lk] : 0.f;
        rb[i] = (lk < K) ? Bb[(long)(bn + m) * ldb + lk] : 0.f;
    }

    for (int k0 = 0; k0 < K; k0 += BK) {
#pragma unroll
        for (int i = 0; i < 4; i++) {
            As[lk][lm + i * 32] = ra[i];
            Bs[lk][lm + i * 32] = rb[i];
        }
        __syncthreads();
        int kn = k0 + BK;
        if (kn < K) {
#pragma unroll
            for (int i = 0; i < 4; i++) {
                int m = lm + i * 32;
                ra[i] = (kn + lk < K) ? Ab[(long)(bm + m) * lda + kn + lk] : 0.f;
                rb[i] = (kn + lk < K) ? Bb[(long)(bn + m) * ldb + kn + lk] : 0.f;
            }
        }
#pragma unroll
        for (int kk = 0; kk < BK; kk++) {
            float4 a0 = *(const float4*)&As[kk][ty * 4];
            float4 a1 = *(const float4*)&As[kk][64 + ty * 4];
            float4 b0 = *(const float4*)&Bs[kk][tx * 4];
            float4 b1 = *(const float4*)&Bs[kk][64 + tx * 4];
            float av[8] = {a0.x, a0.y, a0.z, a0.w, a1.x, a1.y, a1.z, a1.w};
            float bv[8] = {b0.x, b0.y, b0.z, b0.w, b1.x, b1.y, b1.z, b1.w};
#pragma unroll
            for (int i = 0; i < 8; i++)
#pragma unroll
                for (int j = 0; j < 8; j++) acc[i][j] += av[i] * bv[j];
        }
        __syncthreads();
    }

#pragma unroll
    for (int i = 0; i < 8; i++) {
        int m = bm + (i < 4 ? ty * 4 + i : 64 + ty * 4 + (i - 4));
#pragma unroll
        for (int j = 0; j < 8; j++) {
            int n_ = bn + (j < 4 ? tx * 4 + j : 64 + tx * 4 + (j - 4));
            float v = acc[i][j];
            if (mode == 1) {
                v = 2.f * v - d2[(long)blockIdx.z * bsD2 + n_];
            } else if (mode == 2) {
                float gg = bnp[n_], be = bnp[Nn + n_], mm = bnp[2 * Nn + n_], vv = bnp[3 * Nn + n_];
                v = (v - mm) * (gg * rsqrtf(vv + EPS)) + be;
                v = v > 0.f ? v : SLOPE * v;
            }
            Cb[(long)m * ldc + n_] = v;
        }
    }
}

// ---------------- d2 ----------------
__global__ void d2_kernel(const float* __restrict__ X, int ldx, int C,
                          float* __restrict__ d2, int total) {
    int i = blockIdx.x * blockDim.x + threadIdx.x;
    if (i >= total) return;
    const float* xr = X + (long)i * ldx;
    float s = 0.f;
    for (int c = 0; c < C; c++) { float v = xr[c]; s += v * v; }
    d2[i] = s;
}

// ---------------- top-k: one warp per row, register-resident ----------------
__global__ __launch_bounds__(256) void topk_kernel(const float* __restrict__ S,
                                                   int* __restrict__ idxo) {
    int warp = threadIdx.x >> 5, lane = threadIdx.x & 31;
    int row = blockIdx.x * 8 + warp;
    const float* s = S + (long)row * NPTS;

    float r[64];
#pragma unroll
    for (int j = 0; j < 64; j++) r[j] = s[j * 32 + lane];

    for (int it = 0; it < KNN; it++) {
        float best = -INFINITY;
        int bj = 0;
#pragma unroll
        for (int j = 0; j < 64; j++) {
            if (r[j] > best) { best = r[j]; bj = j; }
        }
        int bidx = bj * 32 + lane;
#pragma unroll
        for (int o = 16; o; o >>= 1) {
            float ov = __shfl_down_sync(0xffffffffu, best, o);
            int oi = __shfl_down_sync(0xffffffffu, bidx, o);
            if (ov > best || (ov == best && oi < bidx)) { best = ov; bidx = oi; }
        }
        bidx = __shfl_sync(0xffffffffu, bidx, 0);
        if (lane == 0) idxo[(long)row * KNN + it] = bidx;
        if ((bidx & 31) == lane) {
            int jw = bidx >> 5;
#pragma unroll
            for (int j = 0; j < 64; j++)
                if (j == jw) r[j] = -INFINITY;
        }
    }
}

// ---------------- build effective edge weights (fp32, layer 1) ----------------
__global__ void make_weff(const float* __restrict__ w, int O, int C,
                          float* __restrict__ weff) {
    int i = blockIdx.x * blockDim.x + threadIdx.x;
    if (i >= 2 * O * C) return;
    int row = i / C, c = i % C;
    if (row < O) weff[i] = w[row * 2 * C + c];
    else {
        int o = row - O;
        weff[i] = w[o * 2 * C + C + c] - w[o * 2 * C + c];
    }
}

// ---------------- gather neighbors' Y, max over k, add Z, bn+act ----------------
__global__ void gather_max(const float* __restrict__ YZ, int twoO,
                           const int* __restrict__ idxi,
                           const float* __restrict__ bnp,
                           float* __restrict__ out, int ldo, int O) {
    int n = blockIdx.x, b = blockIdx.y, o = threadIdx.x;
    __shared__ int si[KNN];
    if (o < KNN) si[o] = idxi[((long)b * NPTS + n) * KNN + o];
    __syncthreads();
    const float* Yb = YZ + (long)b * NPTS * twoO;
    float m = -INFINITY;
#pragma unroll 4
    for (int k = 0; k < KNN; k++) m = fmaxf(m, Yb[(long)si[k] * twoO + o]);
    float z = Yb[(long)n * twoO + O + o];
    float t = m + z;
    float gg = bnp[o], be = bnp[O + o], mm = bnp[2 * O + o], vv = bnp[3 * O + o];
    float v = (t - mm) * (gg * rsqrtf(vv + EPS)) + be;
    v = v > 0.f ? v : SLOPE * v;
    out[((long)b * NPTS + n) * ldo + o] = v;
}

// ---------------- global pool ----------------
__global__ void pool_kernel(const float* __restrict__ x5, float* __restrict__ g) {
    int c = blockIdx.x * 256 + threadIdx.x;
    int b = blockIdx.y;
    const float* p = x5 + (long)b * NPTS * 1024 + c;
    float mx = -INFINITY, sm = 0.f;
    for (int n = 0; n < NPTS; n++) {
        float v = p[(long)n * 1024];
        mx = fmaxf(mx, v);
        sm += v;
    }
    g[b * 2048 + c] = mx;
    g[b * 2048 + 1024 + c] = sm * (1.0f / NPTS);
}

// ---------------- small FC ----------------
__global__ void fc_kernel(const float* __restrict__ in, int K,
                          const float* __restrict__ W,
                          const float* __restrict__ bias,
                          const float* __restrict__ bnp, int useAct,
                          float* __restrict__ out, int O) {
    int o = blockIdx.x, b = blockIdx.y, t = threadIdx.x;
    const float* xr = in + (long)b * K;
    const float* wr = W + (long)o * K;
    float s = 0.f;
    for (int k = t; k < K; k += 128) s += xr[k] * wr[k];
    __shared__ float red[4];
#pragma unroll
    for (int off = 16; off; off >>= 1) s += __shfl_down_sync(0xffffffffu, s, off);
    if ((t & 31) == 0) red[t >> 5] = s;
    __syncthreads();
    if (t == 0) {
        float tot = red[0] + red[1] + red[2] + red[3];
        if (bias) tot += bias[o];
        if (bnp) {
            float gg = bnp[o], be = bnp[O + o], mm = bnp[2 * O + o], vv = bnp[3 * O + o];
            tot = (tot - mm) * (gg * rsqrtf(vv + EPS)) + be;
        }
        if (useAct) tot = tot > 0.f ? tot : SLOPE * tot;
        out[(long)b * O + o] = tot;
    }
}

extern "C" void kernel_launch(void* const* d_in, const int* in_sizes, int n_in,
                              void* d_out, int out_size) {
    const float* x   = (const float*)d_in[0];
    const float* w1  = (const float*)d_in[2];
    const float* w2  = (const float*)d_in[3];
    const float* w3  = (const float*)d_in[4];
    const float* w4  = (const float*)d_in[5];
    const float* w5  = (const float*)d_in[6];
    const float* wl1 = (const float*)d_in[7];
    const float* wl2 = (const float*)d_in[8];
    const float* bl2 = (const float*)d_in[9];
    const float* wl3 = (const float*)d_in[10];
    const float* bl3 = (const float*)d_in[11];
    const float* bn1 = (const float*)d_in[12];
    const float* bn2 = (const float*)d_in[13];
    const float* bn3 = (const float*)d_in[14];
    const float* bn4 = (const float*)d_in[15];
    const float* bn5 = (const float*)d_in[16];
    const float* bn6 = (const float*)d_in[17];
    const float* bn7 = (const float*)d_in[18];

    float *S, *d2, *YZ, *xc, *x5, *weff, *gb, *h1, *h2;
    int* idx;
    unsigned short *Xh, *Xl, *XCh, *XCl, *W5h, *W5l, *Wh, *Wl;
    cudaGetSymbolAddress((void**)&S, g_S);
    cudaGetSymbolAddress((void**)&d2, g_d2);
    cudaGetSymbolAddress((void**)&idx, g_idx);
    cudaGetSymbolAddress((void**)&YZ, g_YZ);
    cudaGetSymbolAddress((void**)&xc, g_xc);
    cudaGetSymbolAddress((void**)&x5, g_x5);
    cudaGetSymbolAddress((void**)&weff, g_weff);
    cudaGetSymbolAddress((void**)&gb, g_g);
    cudaGetSymbolAddress((void**)&h1, g_h1);
    cudaGetSymbolAddress((void**)&h2, g_h2);
    cudaGetSymbolAddress((void**)&Xh, g_Xh);
    cudaGetSymbolAddress((void**)&Xl, g_Xl);
    cudaGetSymbolAddress((void**)&XCh, g_XCh);
    cudaGetSymbolAddress((void**)&XCl, g_XCl);
    cudaGetSymbolAddress((void**)&W5h, g_W5h);
    cudaGetSymbolAddress((void**)&W5l, g_W5l);
    cudaGetSymbolAddress((void**)&Wh, g_Wh);
    cudaGetSymbolAddress((void**)&Wl, g_Wl);

    const int TOTAL = BSZ * NPTS;  // 16384

    // ---------- layer 1 (exact fp32; K=3) ----------
    d2_kernel<<<TOTAL / 256, 256>>>(x, 3, 3, d2, TOTAL);
    gemm_abT<<<dim3(NPTS / BN, NPTS / BM, BSZ), 256>>>(
        x, 3, (long)NPTS * 3, x, 3, (long)NPTS * 3,
        S, NPTS, (long)NPTS * NPTS, NPTS, NPTS, 3, d2, NPTS, nullptr, 1);
    topk_kernel<<<TOTAL / 8, 256>>>(S, idx);
    make_weff<<<(2 * 64 * 3 + 255) / 256, 256>>>(w1, 64, 3, weff);
    gemm_abT<<<dim3(128 / BN, TOTAL / BM, 1), 256>>>(
        x, 3, 0, weff, 3, 0, YZ, 128, 0, TOTAL, 128, 3, nullptr, 0, nullptr, 0);
    gather_max<<<dim3(NPTS, BSZ), 64>>>(YZ, 128, idx, bn1, xc + 0, 512, 64);

    // ---------- layers 2-4 (HMMA fp16-split) ----------
    struct L { int off, C, O; const float* w; const float* bn; };
    L Ls[3] = { {0, 64, 64, w2, bn2}, {64, 64, 128, w3, bn3}, {128, 128, 256, w4, bn4} };
    for (int l = 0; l < 3; l++) {
        const L& c = Ls[l];
        d2_kernel<<<TOTAL / 256, 256>>>(xc + c.off, 512, c.C, d2, TOTAL);
        split_kernel<<<(int)(((long)TOTAL * c.C + 255) / 256), 256>>>(
            xc + c.off, 512, c.C, TOTAL, Xh, Xl);
        // gram: batched [2048 x 2048], K = C
        gemm_mma<<<dim3(16, 16, BSZ), 256>>>(
            Xh, Xl, (long)NPTS * c.C, Xh, Xl, (long)NPTS * c.C,
            S, NPTS, (long)NPTS * NPTS, c.C, d2, nullptr, NPTS, 1);
        topk_kernel<<<TOTAL / 8, 256>>>(S, idx);
        make_weff_split<<<(2 * c.O * c.C + 255) / 256, 256>>>(c.w, c.O, c.C, Wh, Wl);
        // YZ = X * Weff^T : [16384 x 2O]
        gemm_mma<<<dim3(2 * c.O / 128, TOTAL / 128, 1), 256>>>(
            Xh, Xl, 0, Wh, Wl, 0,
            YZ, 2 * c.O, 0, c.C, nullptr, nullptr, 2 * c.O, 0);
        int outoff = (l == 0) ? 64 : (l == 1) ? 128 : 256;
        gather_max<<<dim3(NPTS, BSZ), c.O>>>(YZ, 2 * c.O, idx, c.bn, xc + outoff, 512, c.O);
    }

    // ---------- x5 = act(bn5(xc @ w5^T)) via HMMA ----------
    split_kernel<<<(int)(((long)TOTAL * 512 + 255) / 256), 256>>>(xc, 512, 512, TOTAL, XCh, XCl);
    split_kernel<<<(1024 * 512 + 255) / 256, 256>>>(w5, 512, 512, 1024, W5h, W5l);
    gemm_mma<<<dim3(8, TOTAL / 128, 1), 256>>>(
        XCh, XCl, 0, W5h, W5l, 0,
        x5, 1024, 0, 512, nullptr, bn5, 1024, 2);

    pool_kernel<<<dim3(4, BSZ), 256>>>(x5, gb);

    fc_kernel<<<dim3(512, BSZ), 128>>>(gb, 2048, wl1, nullptr, bn6, 1, h1, 512);
    fc_kernel<<<dim3(256, BSZ), 128>>>(h1, 512, wl2, bl2, bn7, 1, h2, 256);
    fc_kernel<<<dim3(40, BSZ), 128>>>(h2, 256, wl3, bl3, nullptr, 0, (float*)d_out, 40);
}